// round 14
// baseline (speedup 1.0000x reference)
#include <cuda_runtime.h>
#include <cuda_fp16.h>
#include <cstdint>

#define N_NODES 100000
#define E_EDGES 1600000
#define D 64

#define SCAN_T 256
#define SCAN_ELEMS 2048                 // 8 per thread
#define NB_SCAN ((N_NODES + SCAN_ELEMS - 1) / SCAN_ELEMS)   // 49

typedef unsigned long long ull;

// ---------------- scratch (device globals; no allocation allowed) ----------
__device__ int    g_cnt[N_NODES];
__device__ int    g_off[N_NODES + 1];
__device__ int    g_cursor[N_NODES];
__device__ int    g_src_sorted[E_EDGES];
__device__ int    g_partial[64];
__device__ int    g_is64;                // 1 if edge_index is int64, 0 if int32
__device__ __half g_y[(size_t)N_NODES * D];   // fp16: halves gather traffic
__device__ float  g_z[(size_t)N_NODES * D];   // z = x@Wr^T + bias (bias folded)
__device__ float  g_h[(size_t)N_NODES * D];

// ---------------- f32x2 packed helpers (Blackwell FFMA2) --------------------
__device__ __forceinline__ void fma2(ull& d, ull a, ull b) {
    asm("fma.rn.f32x2 %0, %1, %2, %0;" : "+l"(d) : "l"(a), "l"(b));
}
__device__ __forceinline__ float2 u2f2(ull v) {
    float2 r;
    asm("mov.b64 {%0, %1}, %2;" : "=f"(r.x), "=f"(r.y) : "l"(v));
    return r;
}

__device__ __forceinline__ int edge_val(const int* ei32, long long idx) {
    if (g_is64) return (int)((const long long*)ei32)[idx];
    return ei32[idx];
}

// ---------------- init: zero counters + dtype probe + constant tail ---------
__global__ void k_init(const int* __restrict__ ei32) {
    int i = blockIdx.x * blockDim.x + threadIdx.x;
    if (i < N_NODES) g_cnt[i] = 0;
    if (i == 0) {
        g_off[N_NODES] = E_EDGES;
        int nz_hi = 0;
#pragma unroll 1
        for (int k = 0; k < 64; k++) {
            if (ei32[2 * k + 1] != 0) nz_hi++;
        }
        g_is64 = (nz_hi == 0) ? 1 : 0;   // int64 high words are all zero
    }
}

// ---------------- CSR build ------------------------------------------------
__global__ void k_hist(const int* __restrict__ ei32) {
    int e = blockIdx.x * blockDim.x + threadIdx.x;
    if (e < E_EDGES) {
        int d = edge_val(ei32, (long long)E_EDGES + e);   // dst
        atomicAdd(&g_cnt[d], 1);
    }
}

__global__ void k_scan1() {
    int base = blockIdx.x * SCAN_ELEMS + threadIdx.x * 8;
    int s = 0;
#pragma unroll
    for (int u = 0; u < 8; u++) {
        int i = base + u;
        if (i < N_NODES) s += g_cnt[i];
    }
    __shared__ int sh[SCAN_T];
    sh[threadIdx.x] = s;
    __syncthreads();
    for (int st = SCAN_T / 2; st > 0; st >>= 1) {
        if (threadIdx.x < st) sh[threadIdx.x] += sh[threadIdx.x + st];
        __syncthreads();
    }
    if (threadIdx.x == 0) g_partial[blockIdx.x] = sh[0];
}

// scan3 with the cross-block prefix computed inline per block (<=48 LDGs).
__global__ void k_scan3() {
    __shared__ int sh[SCAN_T];
    __shared__ int s_base;
    if (threadIdx.x == 0) {
        int acc = 0;
#pragma unroll 1
        for (int b = 0; b < blockIdx.x; b++) acc += g_partial[b];
        s_base = acc;
    }
    int base = blockIdx.x * SCAN_ELEMS + threadIdx.x * 8;
    int loc[8];
    int s = 0;
#pragma unroll
    for (int u = 0; u < 8; u++) {
        int i = base + u;
        loc[u] = (i < N_NODES) ? g_cnt[i] : 0;
        s += loc[u];
    }
    sh[threadIdx.x] = s;
    __syncthreads();
    for (int st = 1; st < SCAN_T; st <<= 1) {
        int v = 0;
        if (threadIdx.x >= st) v = sh[threadIdx.x - st];
        __syncthreads();
        sh[threadIdx.x] += v;
        __syncthreads();
    }
    int pre = s_base + sh[threadIdx.x] - s;  // exclusive prefix
#pragma unroll
    for (int u = 0; u < 8; u++) {
        int i = base + u;
        if (i < N_NODES) {
            g_off[i] = pre;
            g_cursor[i] = pre;
            pre += loc[u];
        }
    }
}

__global__ void k_scatter(const int* __restrict__ ei32) {
    int e = blockIdx.x * blockDim.x + threadIdx.x;
    if (e < E_EDGES) {
        int d = edge_val(ei32, (long long)E_EDGES + e);
        int s = edge_val(ei32, e);
        int p = atomicAdd(&g_cursor[d], 1);
        g_src_sorted[p] = s;
    }
}

// ---------------- fused dual GEMM (packed f32x2 FMA) ------------------------
// Y = X @ Wl^T (fp16 out), Z = X @ Wr^T + bias (fp32 out). One thread per row.
// K-pair packing: a = {x_k, x_{k+1}} free from reading X row as u64,
// b = {w[f][k], w[f][k+1]} adjacent in row-major W -> LDS.128 + FFMA2 loop.
template <bool HALF_OUT>
__device__ __forceinline__ void gemm_row_f32x2(
    const float* __restrict__ Wsh,
    const ull* __restrict__ xq,
    void* __restrict__ outp, size_t row,
    const float* __restrict__ bias)      // nullptr for the fp16 (Y) path
{
#pragma unroll 1
    for (int f0 = 0; f0 < D; f0 += 8) {
        ull acc[8];
#pragma unroll
        for (int u = 0; u < 8; u++) acc[u] = 0ULL;
#pragma unroll
        for (int k4 = 0; k4 < 16; k4++) {
#pragma unroll
            for (int u = 0; u < 8; u++) {
                ulonglong2 w = *(const ulonglong2*)&Wsh[(f0 + u) * D + k4 * 4];
                fma2(acc[u], xq[2 * k4],     w.x);
                fma2(acc[u], xq[2 * k4 + 1], w.y);
            }
        }
        float o[8];
#pragma unroll
        for (int u = 0; u < 8; u++) {
            float2 p = u2f2(acc[u]);
            o[u] = p.x + p.y;
        }
        if (HALF_OUT) {
            __half* out = (__half*)outp + row * D + f0;
            union { uint4 u4; __half2 h[4]; } pk;
            pk.h[0] = __floats2half2_rn(o[0], o[1]);
            pk.h[1] = __floats2half2_rn(o[2], o[3]);
            pk.h[2] = __floats2half2_rn(o[4], o[5]);
            pk.h[3] = __floats2half2_rn(o[6], o[7]);
            *(uint4*)out = pk.u4;
        } else {
            float4 b0 = *(const float4*)&bias[f0];
            float4 b1 = *(const float4*)&bias[f0 + 4];
            float* out = (float*)outp + row * D + f0;
            *(float4*)&out[0] = make_float4(o[0] + b0.x, o[1] + b0.y, o[2] + b0.z, o[3] + b0.w);
            *(float4*)&out[4] = make_float4(o[4] + b1.x, o[5] + b1.y, o[6] + b1.z, o[7] + b1.w);
        }
    }
}

template <int LAYER>
__global__ void __launch_bounds__(128) k_gemm_dual(
    const float* __restrict__ Xin,
    const float* __restrict__ Wl,
    const float* __restrict__ Wr,
    const float* __restrict__ bias)
{
    __shared__ float swl[D * D];
    __shared__ float swr[D * D];
    for (int i = threadIdx.x; i < D * D; i += 128) {
        swl[i] = Wl[i];
        swr[i] = Wr[i];
    }
    __syncthreads();

    int row = blockIdx.x * 128 + threadIdx.x;
    if (row >= N_NODES) return;

    const float* X = (LAYER == 0) ? Xin : (const float*)g_h;

    ull xq[32];
    const ulonglong2* xp = (const ulonglong2*)(X + (size_t)row * D);
#pragma unroll
    for (int i = 0; i < 16; i++) {
        ulonglong2 t = xp[i];
        xq[2 * i]     = t.x;
        xq[2 * i + 1] = t.y;
    }

    gemm_row_f32x2<true >(swl, xq, (void*)g_y, (size_t)row, nullptr);
    gemm_row_f32x2<false>(swr, xq, (void*)g_z, (size_t)row, bias);
}

// ---------------- gather-mean + combine ------------------------------------
// One warp per node; QUARTER-warp (8 lanes x uint4 = 128B) per gathered fp16
// row: one LDG.128 instruction fetches 4 rows (512B), one SHFL with per-lane
// source (t + quarter) delivers 4 edge indices. 16-edge unroll -> 4 LDG.128
// in flight per lane. fp32 accumulation (8 floats/lane), cross-quarter
// reduce via shfl.xor(8) + shfl.xor(16).
__device__ __forceinline__ void h8_acc(float4& a0, float4& a1, uint4 u) {
    float2 f0 = __half22float2(*(__half2*)&u.x);
    float2 f1 = __half22float2(*(__half2*)&u.y);
    float2 f2 = __half22float2(*(__half2*)&u.z);
    float2 f3 = __half22float2(*(__half2*)&u.w);
    a0.x += f0.x; a0.y += f0.y; a0.z += f1.x; a0.w += f1.y;
    a1.x += f2.x; a1.y += f2.y; a1.z += f3.x; a1.w += f3.y;
}

template <int LAYER>
__global__ void __launch_bounds__(256) k_agg(float* __restrict__ OutParam)
{
    int gwarp = (blockIdx.x * blockDim.x + threadIdx.x) >> 5;
    int lane  = threadIdx.x & 31;
    if (gwarp >= N_NODES) return;

    int quarter = lane >> 3;   // which edge of the group of 4
    int sub     = lane & 7;    // 16B chunk within the 128B fp16 row

    int beg = g_off[gwarp];
    int end = g_off[gwarp + 1];

    const __half* Yh = g_y;

    float4 a0 = make_float4(0.f, 0.f, 0.f, 0.f);
    float4 a1 = make_float4(0.f, 0.f, 0.f, 0.f);

    for (int j = beg; j < end; j += 32) {
        int idx = (j + lane < end) ? g_src_sorted[j + lane] : 0;
        int m = min(32, end - j);
        int t = 0;
        // 16 edges per iteration: 4 LDG.128 in flight per lane
        for (; t + 16 <= m; t += 16) {
            int s0 = __shfl_sync(0xffffffffu, idx, t      + quarter);
            int s1 = __shfl_sync(0xffffffffu, idx, t + 4  + quarter);
            int s2 = __shfl_sync(0xffffffffu, idx, t + 8  + quarter);
            int s3 = __shfl_sync(0xffffffffu, idx, t + 12 + quarter);
            uint4 u0 = *(const uint4*)(Yh + (size_t)s0 * D + sub * 8);
            uint4 u1 = *(const uint4*)(Yh + (size_t)s1 * D + sub * 8);
            uint4 u2 = *(const uint4*)(Yh + (size_t)s2 * D + sub * 8);
            uint4 u3 = *(const uint4*)(Yh + (size_t)s3 * D + sub * 8);
            h8_acc(a0, a1, u0);
            h8_acc(a0, a1, u1);
            h8_acc(a0, a1, u2);
            h8_acc(a0, a1, u3);
        }
        for (; t + 4 <= m; t += 4) {
            int s = __shfl_sync(0xffffffffu, idx, t + quarter);
            uint4 u = *(const uint4*)(Yh + (size_t)s * D + sub * 8);
            h8_acc(a0, a1, u);
        }
        if (t < m) {
            int s = __shfl_sync(0xffffffffu, idx, min(t + quarter, m - 1));
            if (t + quarter < m) {
                uint4 u = *(const uint4*)(Yh + (size_t)s * D + sub * 8);
                h8_acc(a0, a1, u);
            }
        }
    }

    // combine the four quarter-warp partial sums
#pragma unroll
    for (int sh = 8; sh <= 16; sh <<= 1) {
        a0.x += __shfl_xor_sync(0xffffffffu, a0.x, sh);
        a0.y += __shfl_xor_sync(0xffffffffu, a0.y, sh);
        a0.z += __shfl_xor_sync(0xffffffffu, a0.z, sh);
        a0.w += __shfl_xor_sync(0xffffffffu, a0.w, sh);
        a1.x += __shfl_xor_sync(0xffffffffu, a1.x, sh);
        a1.y += __shfl_xor_sync(0xffffffffu, a1.y, sh);
        a1.z += __shfl_xor_sync(0xffffffffu, a1.z, sh);
        a1.w += __shfl_xor_sync(0xffffffffu, a1.w, sh);
    }

    if (quarter == 0) {
        float inv = (end > beg) ? 1.0f / (float)(end - beg) : 0.0f;
        const float* zp = (const float*)g_z + (size_t)gwarp * D + sub * 8;
        float4 z0 = *(const float4*)&zp[0];
        float4 z1 = *(const float4*)&zp[4];
        float o0 = a0.x * inv + z0.x;
        float o1 = a0.y * inv + z0.y;
        float o2 = a0.z * inv + z0.z;
        float o3 = a0.w * inv + z0.w;
        float o4 = a1.x * inv + z1.x;
        float o5 = a1.y * inv + z1.y;
        float o6 = a1.z * inv + z1.z;
        float o7 = a1.w * inv + z1.w;
        if (LAYER == 0) {
            o0 = fmaxf(o0, 0.0f); o1 = fmaxf(o1, 0.0f);
            o2 = fmaxf(o2, 0.0f); o3 = fmaxf(o3, 0.0f);
            o4 = fmaxf(o4, 0.0f); o5 = fmaxf(o5, 0.0f);
            o6 = fmaxf(o6, 0.0f); o7 = fmaxf(o7, 0.0f);
        }
        float* Out = (LAYER == 0) ? (float*)g_h : OutParam;
        float* op = Out + (size_t)gwarp * D + sub * 8;
        *(float4*)&op[0] = make_float4(o0, o1, o2, o3);
        *(float4*)&op[4] = make_float4(o4, o5, o6, o7);
    }
}

// ---------------- launch ----------------------------------------------------
extern "C" void kernel_launch(void* const* d_in, const int* in_sizes, int n_in,
                              void* d_out, int out_size)
{
    const float* x   = (const float*)d_in[0];
    const int*   ei  = (const int*)d_in[1];     // edge_index (probe handles int32/int64)
    const float* wl1 = (const float*)d_in[2];
    const float* bl1 = (const float*)d_in[3];
    const float* wr1 = (const float*)d_in[4];
    const float* wl2 = (const float*)d_in[5];
    const float* bl2 = (const float*)d_in[6];
    const float* wr2 = (const float*)d_in[7];
    float* out = (float*)d_out;

    const int TB = 256;
    int nbN   = (N_NODES + TB - 1) / TB;        // 391
    int nbE   = (E_EDGES + TB - 1) / TB;        // 6250
    int nbAgg = (N_NODES * 32 + TB - 1) / TB;   // 12500
    int nbG   = (N_NODES + 127) / 128;          // 782

    // CSR build
    k_init<<<nbN, TB>>>(ei);
    k_hist<<<nbE, TB>>>(ei);
    k_scan1<<<NB_SCAN, SCAN_T>>>();
    k_scan3<<<NB_SCAN, SCAN_T>>>();
    k_scatter<<<nbE, TB>>>(ei);

    // Layer 1: y = x@wl1^T (fp16), z = x@wr1^T + b1 ; h = relu(mean(y)+z)
    k_gemm_dual<0><<<nbG, 128>>>(x, wl1, wr1, bl1);
    k_agg<0><<<nbAgg, TB>>>(nullptr);

    // Layer 2: y = h@wl2^T (fp16), z = h@wr2^T + b2 ; out = mean(y)+z
    k_gemm_dual<1><<<nbG, 128>>>(nullptr, wl2, wr2, bl2);
    k_agg<1><<<nbAgg, TB>>>(out);
}

// round 15
// speedup vs baseline: 1.0101x; 1.0101x over previous
#include <cuda_runtime.h>
#include <cuda_fp16.h>
#include <cstdint>

#define N_NODES 100000
#define E_EDGES 1600000
#define D 64

#define SCAN_T 256
#define SCAN_ELEMS 2048                 // 8 per thread
#define NB_SCAN ((N_NODES + SCAN_ELEMS - 1) / SCAN_ELEMS)   // 49

typedef unsigned long long ull;

// ---------------- scratch (device globals; no allocation allowed) ----------
// NOTE: g_cnt relies on zero-init at module load; k_scan3 re-zeros it after
// consuming it, so every run (and every graph replay) sees zeros.
__device__ int    g_cnt[N_NODES];
__device__ int    g_off[N_NODES + 1];
__device__ int    g_cursor[N_NODES];
__device__ int    g_src_sorted[E_EDGES];
__device__ int    g_partial[64];
__device__ int    g_is64;                // 1 if edge_index is int64, 0 if int32
__device__ __half g_y[(size_t)N_NODES * D];   // fp16: halves gather traffic
__device__ __half g_z[(size_t)N_NODES * D];   // fp16: z = x@Wr^T + bias (folded)
__device__ float  g_h[(size_t)N_NODES * D];

// ---------------- f32x2 packed helpers (Blackwell FFMA2) --------------------
__device__ __forceinline__ void fma2(ull& d, ull a, ull b) {
    asm("fma.rn.f32x2 %0, %1, %2, %0;" : "+l"(d) : "l"(a), "l"(b));
}
__device__ __forceinline__ float2 u2f2(ull v) {
    float2 r;
    asm("mov.b64 {%0, %1}, %2;" : "=f"(r.x), "=f"(r.y) : "l"(v));
    return r;
}

__device__ __forceinline__ int edge_val(const int* ei32, long long idx) {
    if (g_is64) return (int)((const long long*)ei32)[idx];
    return ei32[idx];
}

// ---------------- probe: edge_index dtype + constant tail -------------------
// int64 indices < 2^31 -> every high word is 0; int32 -> "high words" are
// random indices, nonzero w.h.p.
__global__ void k_probe(const int* __restrict__ ei32) {
    if (threadIdx.x == 0) {
        g_off[N_NODES] = E_EDGES;
        int nz_hi = 0;
#pragma unroll 1
        for (int k = 0; k < 64; k++) {
            if (ei32[2 * k + 1] != 0) nz_hi++;
        }
        g_is64 = (nz_hi == 0) ? 1 : 0;
    }
}

// ---------------- CSR build ------------------------------------------------
__global__ void k_hist(const int* __restrict__ ei32) {
    int e = blockIdx.x * blockDim.x + threadIdx.x;
    if (e < E_EDGES) {
        int d = edge_val(ei32, (long long)E_EDGES + e);   // dst
        atomicAdd(&g_cnt[d], 1);
    }
}

__global__ void k_scan1() {
    int base = blockIdx.x * SCAN_ELEMS + threadIdx.x * 8;
    int s = 0;
#pragma unroll
    for (int u = 0; u < 8; u++) {
        int i = base + u;
        if (i < N_NODES) s += g_cnt[i];
    }
    __shared__ int sh[SCAN_T];
    sh[threadIdx.x] = s;
    __syncthreads();
    for (int st = SCAN_T / 2; st > 0; st >>= 1) {
        if (threadIdx.x < st) sh[threadIdx.x] += sh[threadIdx.x + st];
        __syncthreads();
    }
    if (threadIdx.x == 0) g_partial[blockIdx.x] = sh[0];
}

// scan3: cross-block prefix computed inline per block (<=48 LDGs), then
// writes offsets/cursors AND re-zeros g_cnt for the next run/replay.
__global__ void k_scan3() {
    __shared__ int sh[SCAN_T];
    __shared__ int s_base;
    if (threadIdx.x == 0) {
        int acc = 0;
#pragma unroll 1
        for (int b = 0; b < blockIdx.x; b++) acc += g_partial[b];
        s_base = acc;
    }
    int base = blockIdx.x * SCAN_ELEMS + threadIdx.x * 8;
    int loc[8];
    int s = 0;
#pragma unroll
    for (int u = 0; u < 8; u++) {
        int i = base + u;
        loc[u] = (i < N_NODES) ? g_cnt[i] : 0;
        s += loc[u];
    }
    sh[threadIdx.x] = s;
    __syncthreads();
    for (int st = 1; st < SCAN_T; st <<= 1) {
        int v = 0;
        if (threadIdx.x >= st) v = sh[threadIdx.x - st];
        __syncthreads();
        sh[threadIdx.x] += v;
        __syncthreads();
    }
    int pre = s_base + sh[threadIdx.x] - s;  // exclusive prefix
#pragma unroll
    for (int u = 0; u < 8; u++) {
        int i = base + u;
        if (i < N_NODES) {
            g_off[i] = pre;
            g_cursor[i] = pre;
            g_cnt[i] = 0;                  // self-zero for next run
            pre += loc[u];
        }
    }
}

__global__ void k_scatter(const int* __restrict__ ei32) {
    int e = blockIdx.x * blockDim.x + threadIdx.x;
    if (e < E_EDGES) {
        int d = edge_val(ei32, (long long)E_EDGES + e);
        int s = edge_val(ei32, e);
        int p = atomicAdd(&g_cursor[d], 1);
        g_src_sorted[p] = s;
    }
}

// ---------------- fused dual GEMM (packed f32x2 FMA) ------------------------
// Y = X @ Wl^T (fp16), Z = X @ Wr^T + bias (fp16). One thread per node row.
// K-pair packing: a = {x_k, x_{k+1}} free from reading X row as u64,
// b = {w[f][k], w[f][k+1]} adjacent in row-major W -> LDS.128 + FFMA2 loop.
template <bool BIAS>
__device__ __forceinline__ void gemm_row_f32x2(
    const float* __restrict__ Wsh,
    const ull* __restrict__ xq,
    __half* __restrict__ outp, size_t row,
    const float* __restrict__ bias)
{
#pragma unroll 1
    for (int f0 = 0; f0 < D; f0 += 8) {
        ull acc[8];
#pragma unroll
        for (int u = 0; u < 8; u++) acc[u] = 0ULL;
#pragma unroll
        for (int k4 = 0; k4 < 16; k4++) {
#pragma unroll
            for (int u = 0; u < 8; u++) {
                ulonglong2 w = *(const ulonglong2*)&Wsh[(f0 + u) * D + k4 * 4];
                fma2(acc[u], xq[2 * k4],     w.x);
                fma2(acc[u], xq[2 * k4 + 1], w.y);
            }
        }
        float o[8];
#pragma unroll
        for (int u = 0; u < 8; u++) {
            float2 p = u2f2(acc[u]);
            o[u] = p.x + p.y;
        }
        if (BIAS) {
            float4 b0 = *(const float4*)&bias[f0];
            float4 b1 = *(const float4*)&bias[f0 + 4];
            o[0] += b0.x; o[1] += b0.y; o[2] += b0.z; o[3] += b0.w;
            o[4] += b1.x; o[5] += b1.y; o[6] += b1.z; o[7] += b1.w;
        }
        __half* out = outp + row * D + f0;
        union { uint4 u4; __half2 h[4]; } pk;
        pk.h[0] = __floats2half2_rn(o[0], o[1]);
        pk.h[1] = __floats2half2_rn(o[2], o[3]);
        pk.h[2] = __floats2half2_rn(o[4], o[5]);
        pk.h[3] = __floats2half2_rn(o[6], o[7]);
        *(uint4*)out = pk.u4;
    }
}

template <int LAYER>
__global__ void __launch_bounds__(128) k_gemm_dual(
    const float* __restrict__ Xin,
    const float* __restrict__ Wl,
    const float* __restrict__ Wr,
    const float* __restrict__ bias)
{
    __shared__ float swl[D * D];
    __shared__ float swr[D * D];
    for (int i = threadIdx.x; i < D * D; i += 128) {
        swl[i] = Wl[i];
        swr[i] = Wr[i];
    }
    __syncthreads();

    int row = blockIdx.x * 128 + threadIdx.x;
    if (row >= N_NODES) return;

    const float* X = (LAYER == 0) ? Xin : (const float*)g_h;

    ull xq[32];
    const ulonglong2* xp = (const ulonglong2*)(X + (size_t)row * D);
#pragma unroll
    for (int i = 0; i < 16; i++) {
        ulonglong2 t = xp[i];
        xq[2 * i]     = t.x;
        xq[2 * i + 1] = t.y;
    }

    gemm_row_f32x2<false>(swl, xq, g_y, (size_t)row, nullptr);
    gemm_row_f32x2<true >(swr, xq, g_z, (size_t)row, bias);
}

// ---------------- gather-mean + combine ------------------------------------
// One warp per node; HALF-warp (16 lanes x 8B fp16 = 128B) per gathered row.
// 8-edge unroll -> 4 LDG.64 in flight per lane. fp32 accumulation.
__device__ __forceinline__ float4 h4_to_f4(uint2 v) {
    __half2 h0 = *(__half2*)&v.x;
    __half2 h1 = *(__half2*)&v.y;
    float2 f0 = __half22float2(h0);
    float2 f1 = __half22float2(h1);
    return make_float4(f0.x, f0.y, f1.x, f1.y);
}

template <int LAYER>
__global__ void __launch_bounds__(256) k_agg(float* __restrict__ OutParam)
{
    int gwarp = (blockIdx.x * blockDim.x + threadIdx.x) >> 5;
    int lane  = threadIdx.x & 31;
    if (gwarp >= N_NODES) return;

    int half = lane >> 4;     // which edge of the pair
    int sub  = lane & 15;     // 8B chunk within the 128B fp16 row

    int beg = g_off[gwarp];
    int end = g_off[gwarp + 1];

    const __half* Yh = g_y;

    float4 acc = make_float4(0.f, 0.f, 0.f, 0.f);

    for (int j = beg; j < end; j += 32) {
        int idx = (j + lane < end) ? g_src_sorted[j + lane] : 0;
        int m = min(32, end - j);
        int t = 0;
        // 8 edges per iteration: 4 LDG.64 in flight per lane
        for (; t + 8 <= m; t += 8) {
            int s0 = __shfl_sync(0xffffffffu, idx, t     + half);
            int s1 = __shfl_sync(0xffffffffu, idx, t + 2 + half);
            int s2 = __shfl_sync(0xffffffffu, idx, t + 4 + half);
            int s3 = __shfl_sync(0xffffffffu, idx, t + 6 + half);
            uint2 u0 = *(const uint2*)(Yh + (size_t)s0 * D + sub * 4);
            uint2 u1 = *(const uint2*)(Yh + (size_t)s1 * D + sub * 4);
            uint2 u2 = *(const uint2*)(Yh + (size_t)s2 * D + sub * 4);
            uint2 u3 = *(const uint2*)(Yh + (size_t)s3 * D + sub * 4);
            float4 v0 = h4_to_f4(u0);
            float4 v1 = h4_to_f4(u1);
            float4 v2 = h4_to_f4(u2);
            float4 v3 = h4_to_f4(u3);
            acc.x += (v0.x + v1.x) + (v2.x + v3.x);
            acc.y += (v0.y + v1.y) + (v2.y + v3.y);
            acc.z += (v0.z + v1.z) + (v2.z + v3.z);
            acc.w += (v0.w + v1.w) + (v2.w + v3.w);
        }
        // tail, 2 edges per step (shfl unconditional: full-warp participation)
        for (; t < m; t += 2) {
            int s = __shfl_sync(0xffffffffu, idx, min(t + half, m - 1));
            if (t + half < m) {
                uint2 u = *(const uint2*)(Yh + (size_t)s * D + sub * 4);
                float4 v = h4_to_f4(u);
                acc.x += v.x; acc.y += v.y; acc.z += v.z; acc.w += v.w;
            }
        }
    }

    // combine the two half-warp partial sums
    acc.x += __shfl_xor_sync(0xffffffffu, acc.x, 16);
    acc.y += __shfl_xor_sync(0xffffffffu, acc.y, 16);
    acc.z += __shfl_xor_sync(0xffffffffu, acc.z, 16);
    acc.w += __shfl_xor_sync(0xffffffffu, acc.w, 16);

    if (half == 0) {
        float inv = (end > beg) ? 1.0f / (float)(end - beg) : 0.0f;
        uint2 zu = *(const uint2*)(g_z + (size_t)gwarp * D + sub * 4);
        float4 z = h4_to_f4(zu);
        float o0 = acc.x * inv + z.x;
        float o1 = acc.y * inv + z.y;
        float o2 = acc.z * inv + z.z;
        float o3 = acc.w * inv + z.w;
        float* Out = (LAYER == 0) ? (float*)g_h : OutParam;
        if (LAYER == 0) {
            o0 = fmaxf(o0, 0.0f); o1 = fmaxf(o1, 0.0f);
            o2 = fmaxf(o2, 0.0f); o3 = fmaxf(o3, 0.0f);
        }
        *(float4*)(Out + (size_t)gwarp * D + sub * 4) = make_float4(o0, o1, o2, o3);
    }
}

// ---------------- launch ----------------------------------------------------
extern "C" void kernel_launch(void* const* d_in, const int* in_sizes, int n_in,
                              void* d_out, int out_size)
{
    const float* x   = (const float*)d_in[0];
    const int*   ei  = (const int*)d_in[1];     // edge_index (probe handles int32/int64)
    const float* wl1 = (const float*)d_in[2];
    const float* bl1 = (const float*)d_in[3];
    const float* wr1 = (const float*)d_in[4];
    const float* wl2 = (const float*)d_in[5];
    const float* bl2 = (const float*)d_in[6];
    const float* wr2 = (const float*)d_in[7];
    float* out = (float*)d_out;

    const int TB = 256;
    int nbE   = (E_EDGES + TB - 1) / TB;        // 6250
    int nbAgg = (N_NODES * 32 + TB - 1) / TB;   // 12500
    int nbG   = (N_NODES + 127) / 128;          // 782

    // CSR build (g_cnt is zeroed: module-load init + scan3 self-zero each run)
    k_probe<<<1, 32>>>(ei);
    k_hist<<<nbE, TB>>>(ei);
    k_scan1<<<NB_SCAN, SCAN_T>>>();
    k_scan3<<<NB_SCAN, SCAN_T>>>();
    k_scatter<<<nbE, TB>>>(ei);

    // Layer 1: y = x@wl1^T (fp16), z = x@wr1^T + b1 (fp16) ; h = relu(mean(y)+z)
    k_gemm_dual<0><<<nbG, 128>>>(x, wl1, wr1, bl1);
    k_agg<0><<<nbAgg, TB>>>(nullptr);

    // Layer 2: y = h@wl2^T (fp16), z = h@wr2^T + b2 (fp16) ; out = mean(y)+z
    k_gemm_dual<1><<<nbG, 128>>>(nullptr, wl2, wr2, bl2);
    k_agg<1><<<nbAgg, TB>>>(out);
}

// round 17
// speedup vs baseline: 1.1036x; 1.0927x over previous
#include <cuda_runtime.h>
#include <cuda_fp16.h>
#include <cstdint>

#define N_NODES 100000
#define E_EDGES 1600000
#define D 64

#define SCAN_T 256
#define SCAN_ELEMS 2048                 // 8 per thread
#define NB_SCAN ((N_NODES + SCAN_ELEMS - 1) / SCAN_ELEMS)   // 49

typedef unsigned long long ull;

// ---------------- scratch (device globals; no allocation allowed) ----------
// g_cnt relies on zero-init at module load; k_scan3 re-zeros it after
// consuming it, so every run (and every graph replay) sees zeros.
__device__ int    g_cnt[N_NODES];
__device__ int    g_off[N_NODES + 1];
__device__ int    g_cursor[N_NODES];
__device__ int    g_src_sorted[E_EDGES];
__device__ int    g_partial[64];
__device__ int    g_is64;                // 1 if edge_index is int64, 0 if int32
__device__ __half g_y[(size_t)N_NODES * D];   // fp16: halves gather traffic
__device__ __half g_z[(size_t)N_NODES * D];   // fp16: z = x@Wr^T + bias (folded)
__device__ float  g_h[(size_t)N_NODES * D];

// ---------------- f32x2 packed helpers (Blackwell FFMA2) --------------------
__device__ __forceinline__ void fma2(ull& d, ull a, ull b) {
    asm("fma.rn.f32x2 %0, %1, %2, %0;" : "+l"(d) : "l"(a), "l"(b));
}
__device__ __forceinline__ float2 u2f2(ull v) {
    float2 r;
    asm("mov.b64 {%0, %1}, %2;" : "=f"(r.x), "=f"(r.y) : "l"(v));
    return r;
}

// ---------------- probe: edge_index dtype + constant tail -------------------
// int64 indices < 2^31 -> every high word is 0; int32 -> "high words" are
// random indices, nonzero w.h.p.
__global__ void k_probe(const int* __restrict__ ei32) {
    if (threadIdx.x == 0) {
        g_off[N_NODES] = E_EDGES;
        int nz_hi = 0;
#pragma unroll 1
        for (int k = 0; k < 64; k++) {
            if (ei32[2 * k + 1] != 0) nz_hi++;
        }
        g_is64 = (nz_hi == 0) ? 1 : 0;
    }
}

// ---------------- CSR build ------------------------------------------------
// 2 edges per thread, vectorized loads for both dtypes.
__global__ void k_hist(const int* __restrict__ ei32) {
    int p = blockIdx.x * blockDim.x + threadIdx.x;   // pair index
    int e = p * 2;
    if (e >= E_EDGES) return;
    int d0, d1;
    if (g_is64) {
        longlong2 v = ((const longlong2*)((const long long*)ei32 + E_EDGES))[p];
        d0 = (int)v.x; d1 = (int)v.y;
    } else {
        int2 v = ((const int2*)(ei32 + E_EDGES))[p];
        d0 = v.x; d1 = v.y;
    }
    atomicAdd(&g_cnt[d0], 1);
    if (e + 1 < E_EDGES) atomicAdd(&g_cnt[d1], 1);
}

__global__ void k_scan1() {
    int base = blockIdx.x * SCAN_ELEMS + threadIdx.x * 8;
    int s = 0;
#pragma unroll
    for (int u = 0; u < 8; u++) {
        int i = base + u;
        if (i < N_NODES) s += g_cnt[i];
    }
    __shared__ int sh[SCAN_T];
    sh[threadIdx.x] = s;
    __syncthreads();
    for (int st = SCAN_T / 2; st > 0; st >>= 1) {
        if (threadIdx.x < st) sh[threadIdx.x] += sh[threadIdx.x + st];
        __syncthreads();
    }
    if (threadIdx.x == 0) g_partial[blockIdx.x] = sh[0];
}

// scan3: cross-block prefix computed inline per block (<=48 LDGs), then
// writes offsets/cursors AND re-zeros g_cnt for the next run/replay.
__global__ void k_scan3() {
    __shared__ int sh[SCAN_T];
    __shared__ int s_base;
    if (threadIdx.x == 0) {
        int acc = 0;
#pragma unroll 1
        for (int b = 0; b < blockIdx.x; b++) acc += g_partial[b];
        s_base = acc;
    }
    int base = blockIdx.x * SCAN_ELEMS + threadIdx.x * 8;
    int loc[8];
    int s = 0;
#pragma unroll
    for (int u = 0; u < 8; u++) {
        int i = base + u;
        loc[u] = (i < N_NODES) ? g_cnt[i] : 0;
        s += loc[u];
    }
    sh[threadIdx.x] = s;
    __syncthreads();
    for (int st = 1; st < SCAN_T; st <<= 1) {
        int v = 0;
        if (threadIdx.x >= st) v = sh[threadIdx.x - st];
        __syncthreads();
        sh[threadIdx.x] += v;
        __syncthreads();
    }
    int pre = s_base + sh[threadIdx.x] - s;  // exclusive prefix
#pragma unroll
    for (int u = 0; u < 8; u++) {
        int i = base + u;
        if (i < N_NODES) {
            g_off[i] = pre;
            g_cursor[i] = pre;
            g_cnt[i] = 0;                  // self-zero for next run
            pre += loc[u];
        }
    }
}

__global__ void k_scatter(const int* __restrict__ ei32) {
    int p = blockIdx.x * blockDim.x + threadIdx.x;   // pair index
    int e = p * 2;
    if (e >= E_EDGES) return;
    int s0, s1, d0, d1;
    if (g_is64) {
        const long long* ei64 = (const long long*)ei32;
        longlong2 sv = ((const longlong2*)ei64)[p];
        longlong2 dv = ((const longlong2*)(ei64 + E_EDGES))[p];
        s0 = (int)sv.x; s1 = (int)sv.y;
        d0 = (int)dv.x; d1 = (int)dv.y;
    } else {
        int2 sv = ((const int2*)ei32)[p];
        int2 dv = ((const int2*)(ei32 + E_EDGES))[p];
        s0 = sv.x; s1 = sv.y;
        d0 = dv.x; d1 = dv.y;
    }
    int q0 = atomicAdd(&g_cursor[d0], 1);
    g_src_sorted[q0] = s0;
    if (e + 1 < E_EDGES) {
        int q1 = atomicAdd(&g_cursor[d1], 1);
        g_src_sorted[q1] = s1;
    }
}

// ---------------- fused dual GEMM (packed f32x2 FMA) ------------------------
// Y = X @ Wl^T (fp16), Z = X @ Wr^T + bias (fp16). One thread per node row.
template <bool BIAS>
__device__ __forceinline__ void gemm_row_f32x2(
    const float* __restrict__ Wsh,
    const ull* __restrict__ xq,
    __half* __restrict__ outp, size_t row,
    const float* __restrict__ bias)
{
#pragma unroll 1
    for (int f0 = 0; f0 < D; f0 += 8) {
        ull acc[8];
#pragma unroll
        for (int u = 0; u < 8; u++) acc[u] = 0ULL;
#pragma unroll
        for (int k4 = 0; k4 < 16; k4++) {
#pragma unroll
            for (int u = 0; u < 8; u++) {
                ulonglong2 w = *(const ulonglong2*)&Wsh[(f0 + u) * D + k4 * 4];
                fma2(acc[u], xq[2 * k4],     w.x);
                fma2(acc[u], xq[2 * k4 + 1], w.y);
            }
        }
        float o[8];
#pragma unroll
        for (int u = 0; u < 8; u++) {
            float2 p = u2f2(acc[u]);
            o[u] = p.x + p.y;
        }
        if (BIAS) {
            float4 b0 = *(const float4*)&bias[f0];
            float4 b1 = *(const float4*)&bias[f0 + 4];
            o[0] += b0.x; o[1] += b0.y; o[2] += b0.z; o[3] += b0.w;
            o[4] += b1.x; o[5] += b1.y; o[6] += b1.z; o[7] += b1.w;
        }
        __half* out = outp + row * D + f0;
        union { uint4 u4; __half2 h[4]; } pk;
        pk.h[0] = __floats2half2_rn(o[0], o[1]);
        pk.h[1] = __floats2half2_rn(o[2], o[3]);
        pk.h[2] = __floats2half2_rn(o[4], o[5]);
        pk.h[3] = __floats2half2_rn(o[6], o[7]);
        *(uint4*)out = pk.u4;
    }
}

template <int LAYER>
__global__ void __launch_bounds__(128) k_gemm_dual(
    const float* __restrict__ Xin,
    const float* __restrict__ Wl,
    const float* __restrict__ Wr,
    const float* __restrict__ bias)
{
    __shared__ float swl[D * D];
    __shared__ float swr[D * D];
    for (int i = threadIdx.x; i < D * D; i += 128) {
        swl[i] = Wl[i];
        swr[i] = Wr[i];
    }
    __syncthreads();

    int row = blockIdx.x * 128 + threadIdx.x;
    if (row >= N_NODES) return;

    const float* X = (LAYER == 0) ? Xin : (const float*)g_h;

    ull xq[32];
    const ulonglong2* xp = (const ulonglong2*)(X + (size_t)row * D);
#pragma unroll
    for (int i = 0; i < 16; i++) {
        ulonglong2 t = xp[i];
        xq[2 * i]     = t.x;
        xq[2 * i + 1] = t.y;
    }

    gemm_row_f32x2<false>(swl, xq, g_y, (size_t)row, nullptr);
    gemm_row_f32x2<true >(swr, xq, g_z, (size_t)row, bias);
}

// ---------------- gather-mean + combine ------------------------------------
// One warp per node; HALF-warp (16 lanes x 8B fp16 = 128B) per gathered row.
// 8-edge unroll -> 4 LDG.64 in flight per lane. fp32 accumulation.
__device__ __forceinline__ float4 h4_to_f4(uint2 v) {
    __half2 h0 = *(__half2*)&v.x;
    __half2 h1 = *(__half2*)&v.y;
    float2 f0 = __half22float2(h0);
    float2 f1 = __half22float2(h1);
    return make_float4(f0.x, f0.y, f1.x, f1.y);
}

template <int LAYER>
__global__ void __launch_bounds__(256) k_agg(float* __restrict__ OutParam)
{
    int gwarp = (blockIdx.x * blockDim.x + threadIdx.x) >> 5;
    int lane  = threadIdx.x & 31;
    if (gwarp >= N_NODES) return;

    int half = lane >> 4;     // which edge of the pair
    int sub  = lane & 15;     // 8B chunk within the 128B fp16 row

    int beg = g_off[gwarp];
    int end = g_off[gwarp + 1];

    const __half* Yh = g_y;

    float4 acc = make_float4(0.f, 0.f, 0.f, 0.f);

    for (int j = beg; j < end; j += 32) {
        int idx = (j + lane < end) ? g_src_sorted[j + lane] : 0;
        int m = min(32, end - j);
        int t = 0;
        // 8 edges per iteration: 4 LDG.64 in flight per lane
        for (; t + 8 <= m; t += 8) {
            int s0 = __shfl_sync(0xffffffffu, idx, t     + half);
            int s1 = __shfl_sync(0xffffffffu, idx, t + 2 + half);
            int s2 = __shfl_sync(0xffffffffu, idx, t + 4 + half);
            int s3 = __shfl_sync(0xffffffffu, idx, t + 6 + half);
            uint2 u0 = *(const uint2*)(Yh + (size_t)s0 * D + sub * 4);
            uint2 u1 = *(const uint2*)(Yh + (size_t)s1 * D + sub * 4);
            uint2 u2 = *(const uint2*)(Yh + (size_t)s2 * D + sub * 4);
            uint2 u3 = *(const uint2*)(Yh + (size_t)s3 * D + sub * 4);
            float4 v0 = h4_to_f4(u0);
            float4 v1 = h4_to_f4(u1);
            float4 v2 = h4_to_f4(u2);
            float4 v3 = h4_to_f4(u3);
            acc.x += (v0.x + v1.x) + (v2.x + v3.x);
            acc.y += (v0.y + v1.y) + (v2.y + v3.y);
            acc.z += (v0.z + v1.z) + (v2.z + v3.z);
            acc.w += (v0.w + v1.w) + (v2.w + v3.w);
        }
        // tail, 2 edges per step (shfl unconditional: full-warp participation)
        for (; t < m; t += 2) {
            int s = __shfl_sync(0xffffffffu, idx, min(t + half, m - 1));
            if (t + half < m) {
                uint2 u = *(const uint2*)(Yh + (size_t)s * D + sub * 4);
                float4 v = h4_to_f4(u);
                acc.x += v.x; acc.y += v.y; acc.z += v.z; acc.w += v.w;
            }
        }
    }

    // combine the two half-warp partial sums
    acc.x += __shfl_xor_sync(0xffffffffu, acc.x, 16);
    acc.y += __shfl_xor_sync(0xffffffffu, acc.y, 16);
    acc.z += __shfl_xor_sync(0xffffffffu, acc.z, 16);
    acc.w += __shfl_xor_sync(0xffffffffu, acc.w, 16);

    if (half == 0) {
        float inv = (end > beg) ? 1.0f / (float)(end - beg) : 0.0f;
        uint2 zu = *(const uint2*)(g_z + (size_t)gwarp * D + sub * 4);
        float4 z = h4_to_f4(zu);
        float o0 = acc.x * inv + z.x;
        float o1 = acc.y * inv + z.y;
        float o2 = acc.z * inv + z.z;
        float o3 = acc.w * inv + z.w;
        float* Out = (LAYER == 0) ? (float*)g_h : OutParam;
        if (LAYER == 0) {
            o0 = fmaxf(o0, 0.0f); o1 = fmaxf(o1, 0.0f);
            o2 = fmaxf(o2, 0.0f); o3 = fmaxf(o3, 0.0f);
        }
        *(float4*)(Out + (size_t)gwarp * D + sub * 4) = make_float4(o0, o1, o2, o3);
    }
}

// ---------------- launch ----------------------------------------------------
extern "C" void kernel_launch(void* const* d_in, const int* in_sizes, int n_in,
                              void* d_out, int out_size)
{
    const float* x   = (const float*)d_in[0];
    const int*   ei  = (const int*)d_in[1];     // edge_index (probe handles int32/int64)
    const float* wl1 = (const float*)d_in[2];
    const float* bl1 = (const float*)d_in[3];
    const float* wr1 = (const float*)d_in[4];
    const float* wl2 = (const float*)d_in[5];
    const float* bl2 = (const float*)d_in[6];
    const float* wr2 = (const float*)d_in[7];
    float* out = (float*)d_out;

    const int TB = 256;
    int nbE2  = (E_EDGES / 2 + TB - 1) / TB;    // 3125 (2 edges/thread)
    int nbAgg = (N_NODES * 32 + TB - 1) / TB;   // 12500
    int nbG   = (N_NODES + 127) / 128;          // 782

    // Try to fork the layer-1 GEMM (independent of CSR build) onto a second
    // stream inside the capture: CSR chain and gemm0 run concurrently, join
    // before agg0. Events/streams are host objects — no device allocation.
    cudaStream_t s2 = nullptr;
    cudaEvent_t evRoot = nullptr, evJoin = nullptr;
    bool forked = (cudaStreamCreate(&s2) == cudaSuccess);
    if (forked) forked = (cudaEventCreateWithFlags(&evRoot, cudaEventDisableTiming) == cudaSuccess);
    if (forked) forked = (cudaEventCreateWithFlags(&evJoin, cudaEventDisableTiming) == cudaSuccess);

    // dtype probe first (needed by hist/scatter)
    k_probe<<<1, 32>>>(ei);

    if (forked) forked = (cudaEventRecord(evRoot, 0) == cudaSuccess);
    if (forked) forked = (cudaStreamWaitEvent(s2, evRoot, 0) == cudaSuccess);

    if (forked) {
        // branch B: layer-1 dual GEMM on s2
        k_gemm_dual<0><<<nbG, 128, 0, s2>>>(x, wl1, wr1, bl1);
        forked = (cudaEventRecord(evJoin, s2) == cudaSuccess);
    }

    // branch A: CSR build on the main stream
    k_hist<<<nbE2, TB>>>(ei);
    k_scan1<<<NB_SCAN, SCAN_T>>>();
    k_scan3<<<NB_SCAN, SCAN_T>>>();
    k_scatter<<<nbE2, TB>>>(ei);

    if (forked) {
        forked = (cudaStreamWaitEvent(0, evJoin, 0) == cudaSuccess);
    }
    if (!forked) {
        // serial fallback (also covers any event failure above: relaunching
        // the GEMM here is idempotent — same inputs, same outputs)
        k_gemm_dual<0><<<nbG, 128>>>(x, wl1, wr1, bl1);
    }

    // Layer 1 combine: h = relu(mean(y) + z)
    k_agg<0><<<nbAgg, TB>>>(nullptr);

    // Layer 2: y = h@wl2^T (fp16), z = h@wr2^T + b2 (fp16) ; out = mean(y)+z
    k_gemm_dual<1><<<nbG, 128>>>(nullptr, wl2, wr2, bl2);
    k_agg<1><<<nbAgg, TB>>>(out);

    if (s2)     cudaStreamDestroy(s2);
    if (evRoot) cudaEventDestroy(evRoot);
    if (evJoin) cudaEventDestroy(evJoin);
}